// round 4
// baseline (speedup 1.0000x reference)
#include <cuda_runtime.h>
#include <cstdint>

#define D_MODEL 1024
#define LSEQ    4096
#define BATCH   8
#define NFFT    8192
#define LOG2N   13
#define FFT_THREADS 512

// scratch (device globals; no allocation allowed)
__device__ __align__(16) float g_k [D_MODEL * LSEQ];                 // 16 MB normalized kernel
__device__ __align__(16) float g_gy[(size_t)BATCH * D_MODEL * LSEQ]; // 128 MB gelu(conv) output

__device__ __forceinline__ float2 cmul(float2 a, float2 b) {
    return make_float2(a.x * b.x - a.y * b.y, a.x * b.y + a.y * b.x);
}

// ---------------------------------------------------------------------------
// Kernel A: build k[d, 0:4096] = concat of linearly-interpolated segments,
// then normalize by L2 norm over the 4096 taps. One CTA per d.
// Segments: lengths {64,64,128,256,512,1024,2048}, scales {1,1,2,4,8,16,32}.
// ---------------------------------------------------------------------------
__global__ __launch_bounds__(256) void build_k_kernel(
    const float* __restrict__ k0, const float* __restrict__ k1,
    const float* __restrict__ k2, const float* __restrict__ k3,
    const float* __restrict__ k4, const float* __restrict__ k5,
    const float* __restrict__ k6)
{
    int d = blockIdx.x;
    int tid = threadIdx.x;
    __shared__ float ssrc[7 * 64];
    __shared__ float sred[8];
    __shared__ float sinv;

    const float* ks[7] = {k0, k1, k2, k3, k4, k5, k6};
    for (int t = tid; t < 7 * 64; t += 256) {
        int i = t >> 6, j = t & 63;
        ssrc[t] = ks[i][d * 64 + j];
    }
    __syncthreads();

    float vals[16];
    float acc = 0.0f;
    #pragma unroll
    for (int r = 0; r < 16; r++) {
        int j = tid + r * 256;      // 0..4095
        int i, off, lgs;
        if (j < 64)       { i = 0; off = 0;  lgs = 0; }
        else if (j < 128) { i = 1; off = 64; lgs = 0; }
        else {
            int t2 = 31 - __clz(j >> 6);   // j in [128,4096): t2 in [1,5]
            i = t2 + 1; off = 64 << t2; lgs = t2;
        }
        int jj = j - off;
        float inv_s = 1.0f / (float)(1 << lgs);
        float c = (jj + 0.5f) * inv_s - 0.5f;      // exact (power-of-2 scale)
        c = fminf(fmaxf(c, 0.0f), 63.0f);          // clip BEFORE floor, like reference
        float fl = floorf(c);
        int lo = (int)fl;
        int hi = min(lo + 1, 63);
        float w = c - fl;
        float v = ssrc[i * 64 + lo] * (1.0f - w) + ssrc[i * 64 + hi] * w;
        vals[r] = v;
        acc += v * v;
    }
    // block reduce sum of squares
    #pragma unroll
    for (int o = 16; o; o >>= 1) acc += __shfl_xor_sync(0xFFFFFFFFu, acc, o);
    if ((tid & 31) == 0) sred[tid >> 5] = acc;
    __syncthreads();
    if (tid == 0) {
        float s = 0.0f;
        #pragma unroll
        for (int i = 0; i < 8; i++) s += sred[i];
        sinv = 1.0f / sqrtf(s);
    }
    __syncthreads();
    float inv = sinv;
    #pragma unroll
    for (int r = 0; r < 16; r++)
        g_k[(size_t)d * LSEQ + tid + r * 256] = vals[r] * inv;
}

// ---------------------------------------------------------------------------
// Stockham radix-2 FFT, N=8192, out-of-place ping-pong in SMEM.
// Forward: X[k] = sum x[j] e^{-2pi i jk/N}; INV uses conj twiddles (no 1/N).
// Starts reading bufA; after 13 stages result is in bufB.
// ---------------------------------------------------------------------------
template <bool INV>
__device__ __forceinline__ void fft8192(float2* bufA, float2* bufB,
                                        const float2* __restrict__ tw, int tid)
{
    float2* s = bufA;
    float2* t = bufB;
    for (int st = 0; st < LOG2N; st++) {
        int stride = 1 << st;
        int m = NFFT >> (st + 1);
        #pragma unroll
        for (int r = 0; r < (NFFT / 2) / FFT_THREADS; r++) {
            int i = tid + r * FFT_THREADS;
            int q = i & (stride - 1);
            int p = i >> st;
            float2 a = s[q + stride * p];
            float2 b = s[q + stride * (p + m)];
            float2 w = tw[p << st];
            if (INV) w.y = -w.y;
            float2 vs = make_float2(a.x + b.x, a.y + b.y);
            float2 vd = make_float2(a.x - b.x, a.y - b.y);
            t[q + stride * (2 * p)]     = vs;
            t[q + stride * (2 * p + 1)] = cmul(vd, w);
        }
        __syncthreads();
        float2* tmp = s; s = t; t = tmp;
    }
}

// ---------------------------------------------------------------------------
// Kernel B: one CTA per d. FFT the kernel once (held in SMEM, pre-scaled by
// 1/N), then process the 8 batches as 4 complex-packed pairs:
//   z = u0 + i*u1 ; Z = FFT(z) ; Hermitian split -> U0,U1 ; Y = U*K ;
//   w = IFFT(Y0 + i*Y1) -> y0 = Re(w), y1 = Im(w).
// Epilogue fuses +D[d]*u and exact GELU, writes g_gy.
// ---------------------------------------------------------------------------
__global__ __launch_bounds__(FFT_THREADS) void fft_conv_kernel(
    const float* __restrict__ u, const float* __restrict__ Dvec)
{
    extern __shared__ float2 smem[];
    float2* tw   = smem;                    // 4096 twiddles exp(-2pi i j/N)
    float2* Kf   = smem + 4096;             // 8192 kernel spectrum * (1/N)
    float2* bufA = smem + 4096 + 8192;      // 8192
    float2* bufB = bufA + 8192;             // 8192

    int tid = threadIdx.x;
    int d = blockIdx.x;

    for (int j = tid; j < NFFT / 2; j += FFT_THREADS) {
        float th = (-6.283185307179586f / (float)NFFT) * (float)j;
        float sn, cs;
        sincosf(th, &sn, &cs);
        tw[j] = make_float2(cs, sn);
    }
    for (int j = tid; j < NFFT; j += FFT_THREADS)
        bufA[j] = make_float2(j < LSEQ ? g_k[(size_t)d * LSEQ + j] : 0.0f, 0.0f);
    __syncthreads();

    fft8192<false>(bufA, bufB, tw, tid);
    const float scale = 1.0f / (float)NFFT;
    for (int j = tid; j < NFFT; j += FFT_THREADS) {
        float2 kv = bufB[j];
        Kf[j] = make_float2(kv.x * scale, kv.y * scale);
    }
    __syncthreads();

    float Dd = Dvec[d];
    for (int pr = 0; pr < BATCH / 2; pr++) {
        const float* u0 = u + ((size_t)(2 * pr)     * D_MODEL + d) * LSEQ;
        const float* u1 = u + ((size_t)(2 * pr + 1) * D_MODEL + d) * LSEQ;
        for (int j = tid; j < NFFT; j += FFT_THREADS) {
            float a = (j < LSEQ) ? u0[j] : 0.0f;
            float b = (j < LSEQ) ? u1[j] : 0.0f;
            bufA[j] = make_float2(a, b);
        }
        __syncthreads();
        fft8192<false>(bufA, bufB, tw, tid);   // Z in bufB

        for (int j = tid; j < NFFT; j += FFT_THREADS) {
            int jn = (NFFT - j) & (NFFT - 1);
            float2 z  = bufB[j];
            float2 zc = bufB[jn];
            // U0 = (Z[j] + conj(Z[-j]))/2 ; U1 = -i(Z[j] - conj(Z[-j]))/2
            float2 U0 = make_float2(0.5f * (z.x + zc.x),  0.5f * (z.y - zc.y));
            float2 U1 = make_float2(0.5f * (z.y + zc.y), -0.5f * (z.x - zc.x));
            float2 kv = Kf[j];
            float2 y0 = cmul(U0, kv);
            float2 y1 = cmul(U1, kv);
            bufA[j] = make_float2(y0.x - y1.y, y0.y + y1.x);   // Y0 + i*Y1
        }
        __syncthreads();
        fft8192<true>(bufA, bufB, tw, tid);    // w in bufB (1/N folded into Kf)

        float* g0 = g_gy + ((size_t)(2 * pr)     * D_MODEL + d) * LSEQ;
        float* g1 = g_gy + ((size_t)(2 * pr + 1) * D_MODEL + d) * LSEQ;
        for (int l = tid; l < LSEQ; l += FFT_THREADS) {
            float2 wv = bufB[l];
            float y0 = wv.x + Dd * u0[l];
            float y1 = wv.y + Dd * u1[l];
            g0[l] = 0.5f * y0 * (1.0f + erff(y0 * 0.7071067811865475f));
            g1[l] = 0.5f * y1 * (1.0f + erff(y1 * 0.7071067811865475f));
        }
        __syncthreads();
    }
}

// ---------------------------------------------------------------------------
// Kernel C: out[b,v,l] = sum_u W[v,u] * gy[b,u,l] + bias[v]
// tf32 mma.sync m16n8k8, CTA tile 128x128x32, 8 warps (4x2), warp tile 32x64.
// ---------------------------------------------------------------------------
__device__ __forceinline__ uint32_t f2tf(float f) {
    uint32_t r;
    asm("cvt.rna.tf32.f32 %0, %1;" : "=r"(r) : "f"(f));
    return r;
}

#define GBM 128
#define GBN 128
#define GBK 32

__global__ __launch_bounds__(256) void gemm_kernel(
    const float* __restrict__ Wm, const float* __restrict__ bias,
    float* __restrict__ out)
{
    __shared__ float sA[GBM][GBK + 4];   // [m][k], pad 4 -> conflict-free frag loads
    __shared__ float sB[GBK][GBN + 8];   // [k][n], pad 8

    int tid = threadIdx.x;
    int warp = tid >> 5, lane = tid & 31;
    int gid = lane >> 2, q = lane & 3;
    int wm = (warp & 3) * 32;
    int wn = (warp >> 2) * 64;
    int bm = blockIdx.x, bn = blockIdx.y, bb = blockIdx.z;

    const float* Ag = Wm + (size_t)(bm * GBM) * D_MODEL;
    const float* Bg = g_gy + (size_t)bb * D_MODEL * LSEQ + (size_t)(bn * GBN);

    float acc[2][8][4];
    #pragma unroll
    for (int a = 0; a < 2; a++)
        #pragma unroll
        for (int b = 0; b < 8; b++)
            #pragma unroll
            for (int c = 0; c < 4; c++) acc[a][b][c] = 0.0f;

    for (int kt = 0; kt < D_MODEL; kt += GBK) {
        #pragma unroll
        for (int r = 0; r < 4; r++) {           // A: 128x32 = 1024 float4
            int idx = r * 256 + tid;
            int row = idx >> 3;
            int c4  = (idx & 7) << 2;
            float4 v = *reinterpret_cast<const float4*>(Ag + (size_t)row * D_MODEL + kt + c4);
            sA[row][c4 + 0] = __uint_as_float(f2tf(v.x));
            sA[row][c4 + 1] = __uint_as_float(f2tf(v.y));
            sA[row][c4 + 2] = __uint_as_float(f2tf(v.z));
            sA[row][c4 + 3] = __uint_as_float(f2tf(v.w));
        }
        #pragma unroll
        for (int r = 0; r < 4; r++) {           // B: 32x128 = 1024 float4
            int idx = r * 256 + tid;
            int row = idx >> 5;
            int c4  = (idx & 31) << 2;
            float4 v = *reinterpret_cast<const float4*>(Bg + (size_t)(kt + row) * LSEQ + c4);
            sB[row][c4 + 0] = __uint_as_float(f2tf(v.x));
            sB[row][c4 + 1] = __uint_as_float(f2tf(v.y));
            sB[row][c4 + 2] = __uint_as_float(f2tf(v.z));
            sB[row][c4 + 3] = __uint_as_float(f2tf(v.w));
        }
        __syncthreads();

        #pragma unroll
        for (int kk = 0; kk < GBK; kk += 8) {
            uint32_t afr[2][4];
            #pragma unroll
            for (int mi = 0; mi < 2; mi++) {
                int r0 = wm + mi * 16 + gid;
                afr[mi][0] = __float_as_uint(sA[r0    ][kk + q    ]);
                afr[mi][1] = __float_as_uint(sA[r0 + 8][kk + q    ]);
                afr[mi][2] = __float_as_uint(sA[r0    ][kk + q + 4]);
                afr[mi][3] = __float_as_uint(sA[r0 + 8][kk + q + 4]);
            }
            uint32_t bfr[8][2];
            #pragma unroll
            for (int ni = 0; ni < 8; ni++) {
                int c0 = wn + ni * 8 + gid;
                bfr[ni][0] = __float_as_uint(sB[kk + q    ][c0]);
                bfr[ni][1] = __float_as_uint(sB[kk + q + 4][c0]);
            }
            #pragma unroll
            for (int mi = 0; mi < 2; mi++)
                #pragma unroll
                for (int ni = 0; ni < 8; ni++) {
                    asm volatile(
                        "mma.sync.aligned.m16n8k8.row.col.f32.tf32.tf32.f32 "
                        "{%0,%1,%2,%3}, {%4,%5,%6,%7}, {%8,%9}, {%0,%1,%2,%3};\n"
                        : "+f"(acc[mi][ni][0]), "+f"(acc[mi][ni][1]),
                          "+f"(acc[mi][ni][2]), "+f"(acc[mi][ni][3])
                        : "r"(afr[mi][0]), "r"(afr[mi][1]),
                          "r"(afr[mi][2]), "r"(afr[mi][3]),
                          "r"(bfr[ni][0]), "r"(bfr[ni][1]));
                }
        }
        __syncthreads();
    }

    #pragma unroll
    for (int mi = 0; mi < 2; mi++) {
        int v0 = bm * GBM + wm + mi * 16 + gid;
        int v1 = v0 + 8;
        float b0v = bias[v0], b1v = bias[v1];
        #pragma unroll
        for (int ni = 0; ni < 8; ni++) {
            int col = bn * GBN + wn + ni * 8 + q * 2;
            float2 s0 = make_float2(acc[mi][ni][0] + b0v, acc[mi][ni][1] + b0v);
            float2 s1 = make_float2(acc[mi][ni][2] + b1v, acc[mi][ni][3] + b1v);
            *reinterpret_cast<float2*>(out + ((size_t)bb * D_MODEL + v0) * LSEQ + col) = s0;
            *reinterpret_cast<float2*>(out + ((size_t)bb * D_MODEL + v1) * LSEQ + col) = s1;
        }
    }
}

// ---------------------------------------------------------------------------
extern "C" void kernel_launch(void* const* d_in, const int* in_sizes, int n_in,
                              void* d_out, int out_size)
{
    const float* u  = (const float*)d_in[0];
    const float* k0 = (const float*)d_in[1];
    const float* k1 = (const float*)d_in[2];
    const float* k2 = (const float*)d_in[3];
    const float* k3 = (const float*)d_in[4];
    const float* k4 = (const float*)d_in[5];
    const float* k5 = (const float*)d_in[6];
    const float* k6 = (const float*)d_in[7];
    const float* Dv = (const float*)d_in[8];
    const float* Wm = (const float*)d_in[9];
    const float* bv = (const float*)d_in[10];
    float* out = (float*)d_out;

    build_k_kernel<<<D_MODEL, 256>>>(k0, k1, k2, k3, k4, k5, k6);

    const size_t smem_bytes = (size_t)(4096 + 3 * 8192) * sizeof(float2); // 229376 B
    cudaFuncSetAttribute(fft_conv_kernel,
                         cudaFuncAttributeMaxDynamicSharedMemorySize,
                         (int)smem_bytes);
    fft_conv_kernel<<<D_MODEL, FFT_THREADS, smem_bytes>>>(u, Dv);

    dim3 grid(D_MODEL / GBM, LSEQ / GBN, BATCH);
    gemm_kernel<<<grid, 256>>>(Wm, bv, out);
}

// round 5
// speedup vs baseline: 1.0038x; 1.0038x over previous
#include <cuda_runtime.h>
#include <cstdint>

#define D_MODEL 1024
#define LSEQ    4096
#define BATCH   8
#define NFFT    8192
#define LOG2N   13
#define FFT_THREADS 512

// scratch (device globals; no allocation allowed)
__device__ __align__(16) float g_k [D_MODEL * LSEQ];                 // 16 MB normalized kernel
__device__ __align__(16) float g_gy[(size_t)BATCH * D_MODEL * LSEQ]; // 128 MB gelu(conv) output

__device__ __forceinline__ float2 cmul(float2 a, float2 b) {
    return make_float2(a.x * b.x - a.y * b.y, a.x * b.y + a.y * b.x);
}

// ---------------------------------------------------------------------------
// Kernel A: build k[d, 0:4096] = concat of linearly-interpolated segments,
// then normalize by L2 norm over the 4096 taps. One CTA per d.
// Segments: lengths {64,64,128,256,512,1024,2048}, scales {1,1,2,4,8,16,32}.
// ---------------------------------------------------------------------------
__global__ __launch_bounds__(256) void build_k_kernel(
    const float* __restrict__ k0, const float* __restrict__ k1,
    const float* __restrict__ k2, const float* __restrict__ k3,
    const float* __restrict__ k4, const float* __restrict__ k5,
    const float* __restrict__ k6)
{
    int d = blockIdx.x;
    int tid = threadIdx.x;
    __shared__ float ssrc[7 * 64];
    __shared__ float sred[8];
    __shared__ float sinv;

    const float* ks[7] = {k0, k1, k2, k3, k4, k5, k6};
    for (int t = tid; t < 7 * 64; t += 256) {
        int i = t >> 6, j = t & 63;
        ssrc[t] = ks[i][d * 64 + j];
    }
    __syncthreads();

    float vals[16];
    float acc = 0.0f;
    #pragma unroll
    for (int r = 0; r < 16; r++) {
        int j = tid + r * 256;      // 0..4095
        int i, off, lgs;
        if (j < 64)       { i = 0; off = 0;  lgs = 0; }
        else if (j < 128) { i = 1; off = 64; lgs = 0; }
        else {
            int t2 = 31 - __clz(j >> 6);   // j in [128,4096): t2 in [1,5]
            i = t2 + 1; off = 64 << t2; lgs = t2;
        }
        int jj = j - off;
        float inv_s = 1.0f / (float)(1 << lgs);
        float c = (jj + 0.5f) * inv_s - 0.5f;      // exact (power-of-2 scale)
        c = fminf(fmaxf(c, 0.0f), 63.0f);          // clip BEFORE floor, like reference
        float fl = floorf(c);
        int lo = (int)fl;
        int hi = min(lo + 1, 63);
        float w = c - fl;
        float v = ssrc[i * 64 + lo] * (1.0f - w) + ssrc[i * 64 + hi] * w;
        vals[r] = v;
        acc += v * v;
    }
    // block reduce sum of squares
    #pragma unroll
    for (int o = 16; o; o >>= 1) acc += __shfl_xor_sync(0xFFFFFFFFu, acc, o);
    if ((tid & 31) == 0) sred[tid >> 5] = acc;
    __syncthreads();
    if (tid == 0) {
        float s = 0.0f;
        #pragma unroll
        for (int i = 0; i < 8; i++) s += sred[i];
        sinv = 1.0f / sqrtf(s);
    }
    __syncthreads();
    float inv = sinv;
    #pragma unroll
    for (int r = 0; r < 16; r++)
        g_k[(size_t)d * LSEQ + tid + r * 256] = vals[r] * inv;
}

// ---------------------------------------------------------------------------
// Stockham radix-2 FFT, N=8192, out-of-place ping-pong in SMEM.
// Forward: X[k] = sum x[j] e^{-2pi i jk/N}; INV uses conj twiddles (no 1/N).
// Starts reading bufA; after 13 stages result is in bufB.
// ---------------------------------------------------------------------------
template <bool INV>
__device__ __forceinline__ void fft8192(float2* bufA, float2* bufB,
                                        const float2* __restrict__ tw, int tid)
{
    float2* s = bufA;
    float2* t = bufB;
    for (int st = 0; st < LOG2N; st++) {
        int stride = 1 << st;
        int m = NFFT >> (st + 1);
        #pragma unroll
        for (int r = 0; r < (NFFT / 2) / FFT_THREADS; r++) {
            int i = tid + r * FFT_THREADS;
            int q = i & (stride - 1);
            int p = i >> st;
            float2 a = s[q + stride * p];
            float2 b = s[q + stride * (p + m)];
            float2 w = tw[p << st];
            if (INV) w.y = -w.y;
            float2 vs = make_float2(a.x + b.x, a.y + b.y);
            float2 vd = make_float2(a.x - b.x, a.y - b.y);
            t[q + stride * (2 * p)]     = vs;
            t[q + stride * (2 * p + 1)] = cmul(vd, w);
        }
        __syncthreads();
        float2* tmp = s; s = t; t = tmp;
    }
}

// ---------------------------------------------------------------------------
// Kernel B: one CTA per d. FFT the kernel once (held in SMEM, pre-scaled by
// 1/N), then process the 8 batches as 4 complex-packed pairs:
//   z = u0 + i*u1 ; Z = FFT(z) ; Hermitian split -> U0,U1 ; Y = U*K ;
//   w = IFFT(Y0 + i*Y1) -> y0 = Re(w), y1 = Im(w).
// Epilogue fuses +D[d]*u and exact GELU, writes g_gy.
// ---------------------------------------------------------------------------
__global__ __launch_bounds__(FFT_THREADS) void fft_conv_kernel(
    const float* __restrict__ u, const float* __restrict__ Dvec)
{
    extern __shared__ float2 smem[];
    float2* tw   = smem;                    // 4096 twiddles exp(-2pi i j/N)
    float2* Kf   = smem + 4096;             // 8192 kernel spectrum * (1/N)
    float2* bufA = smem + 4096 + 8192;      // 8192
    float2* bufB = bufA + 8192;             // 8192

    int tid = threadIdx.x;
    int d = blockIdx.x;

    for (int j = tid; j < NFFT / 2; j += FFT_THREADS) {
        float th = (-6.283185307179586f / (float)NFFT) * (float)j;
        float sn, cs;
        sincosf(th, &sn, &cs);
        tw[j] = make_float2(cs, sn);
    }
    for (int j = tid; j < NFFT; j += FFT_THREADS)
        bufA[j] = make_float2(j < LSEQ ? g_k[(size_t)d * LSEQ + j] : 0.0f, 0.0f);
    __syncthreads();

    fft8192<false>(bufA, bufB, tw, tid);
    const float scale = 1.0f / (float)NFFT;
    for (int j = tid; j < NFFT; j += FFT_THREADS) {
        float2 kv = bufB[j];
        Kf[j] = make_float2(kv.x * scale, kv.y * scale);
    }
    __syncthreads();

    float Dd = Dvec[d];
    for (int pr = 0; pr < BATCH / 2; pr++) {
        const float* u0 = u + ((size_t)(2 * pr)     * D_MODEL + d) * LSEQ;
        const float* u1 = u + ((size_t)(2 * pr + 1) * D_MODEL + d) * LSEQ;
        for (int j = tid; j < NFFT; j += FFT_THREADS) {
            float a = (j < LSEQ) ? u0[j] : 0.0f;
            float b = (j < LSEQ) ? u1[j] : 0.0f;
            bufA[j] = make_float2(a, b);
        }
        __syncthreads();
        fft8192<false>(bufA, bufB, tw, tid);   // Z in bufB

        for (int j = tid; j < NFFT; j += FFT_THREADS) {
            int jn = (NFFT - j) & (NFFT - 1);
            float2 z  = bufB[j];
            float2 zc = bufB[jn];
            // U0 = (Z[j] + conj(Z[-j]))/2 ; U1 = -i(Z[j] - conj(Z[-j]))/2
            float2 U0 = make_float2(0.5f * (z.x + zc.x),  0.5f * (z.y - zc.y));
            float2 U1 = make_float2(0.5f * (z.y + zc.y), -0.5f * (z.x - zc.x));
            float2 kv = Kf[j];
            float2 y0 = cmul(U0, kv);
            float2 y1 = cmul(U1, kv);
            bufA[j] = make_float2(y0.x - y1.y, y0.y + y1.x);   // Y0 + i*Y1
        }
        __syncthreads();
        fft8192<true>(bufA, bufB, tw, tid);    // w in bufB (1/N folded into Kf)

        float* g0 = g_gy + ((size_t)(2 * pr)     * D_MODEL + d) * LSEQ;
        float* g1 = g_gy + ((size_t)(2 * pr + 1) * D_MODEL + d) * LSEQ;
        for (int l = tid; l < LSEQ; l += FFT_THREADS) {
            float2 wv = bufB[l];
            float y0 = wv.x + Dd * u0[l];
            float y1 = wv.y + Dd * u1[l];
            g0[l] = 0.5f * y0 * (1.0f + erff(y0 * 0.7071067811865475f));
            g1[l] = 0.5f * y1 * (1.0f + erff(y1 * 0.7071067811865475f));
        }
        __syncthreads();
    }
}

// ---------------------------------------------------------------------------
// Kernel C: out[b,v,l] = sum_u W[v,u] * gy[b,u,l] + bias[v]
// tf32 mma.sync m16n8k8, CTA tile 128x128x32, 8 warps (4x2), warp tile 32x64.
// ---------------------------------------------------------------------------
__device__ __forceinline__ uint32_t f2tf(float f) {
    uint32_t r;
    asm("cvt.rna.tf32.f32 %0, %1;" : "=r"(r) : "f"(f));
    return r;
}

#define GBM 128
#define GBN 128
#define GBK 32

__global__ __launch_bounds__(256) void gemm_kernel(
    const float* __restrict__ Wm, const float* __restrict__ bias,
    float* __restrict__ out)
{
    __shared__ float sA[GBM][GBK + 4];   // [m][k], pad 4 -> conflict-free frag loads
    __shared__ float sB[GBK][GBN + 8];   // [k][n], pad 8

    int tid = threadIdx.x;
    int warp = tid >> 5, lane = tid & 31;
    int gid = lane >> 2, q = lane & 3;
    int wm = (warp & 3) * 32;
    int wn = (warp >> 2) * 64;
    int bm = blockIdx.x, bn = blockIdx.y, bb = blockIdx.z;

    const float* Ag = Wm + (size_t)(bm * GBM) * D_MODEL;
    const float* Bg = g_gy + (size_t)bb * D_MODEL * LSEQ + (size_t)(bn * GBN);

    float acc[2][8][4];
    #pragma unroll
    for (int a = 0; a < 2; a++)
        #pragma unroll
        for (int b = 0; b < 8; b++)
            #pragma unroll
            for (int c = 0; c < 4; c++) acc[a][b][c] = 0.0f;

    for (int kt = 0; kt < D_MODEL; kt += GBK) {
        #pragma unroll
        for (int r = 0; r < 4; r++) {           // A: 128x32 = 1024 float4
            int idx = r * 256 + tid;
            int row = idx >> 3;
            int c4  = (idx & 7) << 2;
            float4 v = *reinterpret_cast<const float4*>(Ag + (size_t)row * D_MODEL + kt + c4);
            sA[row][c4 + 0] = __uint_as_float(f2tf(v.x));
            sA[row][c4 + 1] = __uint_as_float(f2tf(v.y));
            sA[row][c4 + 2] = __uint_as_float(f2tf(v.z));
            sA[row][c4 + 3] = __uint_as_float(f2tf(v.w));
        }
        #pragma unroll
        for (int r = 0; r < 4; r++) {           // B: 32x128 = 1024 float4
            int idx = r * 256 + tid;
            int row = idx >> 5;
            int c4  = (idx & 31) << 2;
            float4 v = *reinterpret_cast<const float4*>(Bg + (size_t)(kt + row) * LSEQ + c4);
            sB[row][c4 + 0] = __uint_as_float(f2tf(v.x));
            sB[row][c4 + 1] = __uint_as_float(f2tf(v.y));
            sB[row][c4 + 2] = __uint_as_float(f2tf(v.z));
            sB[row][c4 + 3] = __uint_as_float(f2tf(v.w));
        }
        __syncthreads();

        #pragma unroll
        for (int kk = 0; kk < GBK; kk += 8) {
            uint32_t afr[2][4];
            #pragma unroll
            for (int mi = 0; mi < 2; mi++) {
                int r0 = wm + mi * 16 + gid;
                afr[mi][0] = __float_as_uint(sA[r0    ][kk + q    ]);
                afr[mi][1] = __float_as_uint(sA[r0 + 8][kk + q    ]);
                afr[mi][2] = __float_as_uint(sA[r0    ][kk + q + 4]);
                afr[mi][3] = __float_as_uint(sA[r0 + 8][kk + q + 4]);
            }
            uint32_t bfr[8][2];
            #pragma unroll
            for (int ni = 0; ni < 8; ni++) {
                int c0 = wn + ni * 8 + gid;
                bfr[ni][0] = __float_as_uint(sB[kk + q    ][c0]);
                bfr[ni][1] = __float_as_uint(sB[kk + q + 4][c0]);
            }
            #pragma unroll
            for (int mi = 0; mi < 2; mi++)
                #pragma unroll
                for (int ni = 0; ni < 8; ni++) {
                    asm volatile(
                        "mma.sync.aligned.m16n8k8.row.col.f32.tf32.tf32.f32 "
                        "{%0,%1,%2,%3}, {%4,%5,%6,%7}, {%8,%9}, {%0,%1,%2,%3};\n"
                        : "+f"(acc[mi][ni][0]), "+f"(acc[mi][ni][1]),
                          "+f"(acc[mi][ni][2]), "+f"(acc[mi][ni][3])
                        : "r"(afr[mi][0]), "r"(afr[mi][1]),
                          "r"(afr[mi][2]), "r"(afr[mi][3]),
                          "r"(bfr[ni][0]), "r"(bfr[ni][1]));
                }
        }
        __syncthreads();
    }

    #pragma unroll
    for (int mi = 0; mi < 2; mi++) {
        int v0 = bm * GBM + wm + mi * 16 + gid;
        int v1 = v0 + 8;
        float b0v = bias[v0], b1v = bias[v1];
        #pragma unroll
        for (int ni = 0; ni < 8; ni++) {
            int col = bn * GBN + wn + ni * 8 + q * 2;
            float2 s0 = make_float2(acc[mi][ni][0] + b0v, acc[mi][ni][1] + b0v);
            float2 s1 = make_float2(acc[mi][ni][2] + b1v, acc[mi][ni][3] + b1v);
            *reinterpret_cast<float2*>(out + ((size_t)bb * D_MODEL + v0) * LSEQ + col) = s0;
            *reinterpret_cast<float2*>(out + ((size_t)bb * D_MODEL + v1) * LSEQ + col) = s1;
        }
    }
}

// ---------------------------------------------------------------------------
extern "C" void kernel_launch(void* const* d_in, const int* in_sizes, int n_in,
                              void* d_out, int out_size)
{
    const float* u  = (const float*)d_in[0];
    const float* k0 = (const float*)d_in[1];
    const float* k1 = (const float*)d_in[2];
    const float* k2 = (const float*)d_in[3];
    const float* k3 = (const float*)d_in[4];
    const float* k4 = (const float*)d_in[5];
    const float* k5 = (const float*)d_in[6];
    const float* k6 = (const float*)d_in[7];
    const float* Dv = (const float*)d_in[8];
    const float* Wm = (const float*)d_in[9];
    const float* bv = (const float*)d_in[10];
    float* out = (float*)d_out;

    build_k_kernel<<<D_MODEL, 256>>>(k0, k1, k2, k3, k4, k5, k6);

    const size_t smem_bytes = (size_t)(4096 + 3 * 8192) * sizeof(float2); // 229376 B
    cudaFuncSetAttribute(fft_conv_kernel,
                         cudaFuncAttributeMaxDynamicSharedMemorySize,
                         (int)smem_bytes);
    fft_conv_kernel<<<D_MODEL, FFT_THREADS, smem_bytes>>>(u, Dv);

    dim3 grid(D_MODEL / GBM, LSEQ / GBN, BATCH);
    gemm_kernel<<<grid, 256>>>(Wm, bv, out);
}

// round 6
// speedup vs baseline: 1.3599x; 1.3548x over previous
#include <cuda_runtime.h>
#include <cstdint>

#define D_MODEL 1024
#define LSEQ    4096
#define BATCH   8
#define NFFT    8192
#define FFT_THREADS 1024

// padded SMEM index: +1 float2 every 16 float2 (breaks stride-8/64 store conflicts)
#define PAD(i) ((i) + ((i) >> 4))

// scratch (device globals; no allocation allowed)
__device__ __align__(16) float g_k [D_MODEL * LSEQ];                 // 16 MB normalized kernel
__device__ __align__(16) float g_gy[(size_t)BATCH * D_MODEL * LSEQ]; // 128 MB gelu(conv) output

__device__ __forceinline__ float2 cmul(float2 a, float2 b) {
    return make_float2(a.x * b.x - a.y * b.y, a.x * b.y + a.y * b.x);
}
__device__ __forceinline__ float2 cadd(float2 a, float2 b) { return make_float2(a.x + b.x, a.y + b.y); }
__device__ __forceinline__ float2 csub(float2 a, float2 b) { return make_float2(a.x - b.x, a.y - b.y); }

// rotation by -i (fwd) / +i (inv)
template <bool INV> __device__ __forceinline__ float2 rot90(float2 z) {
    return INV ? make_float2(-z.y, z.x) : make_float2(z.y, -z.x);
}
// rotation by W8^1 = exp(-i pi/4) (fwd) or its conjugate (inv)
template <bool INV> __device__ __forceinline__ float2 rotW81(float2 z) {
    const float s = 0.70710678118654752440f;
    return INV ? make_float2(s * (z.x - z.y), s * (z.y + z.x))
               : make_float2(s * (z.x + z.y), s * (z.y - z.x));
}
// rotation by W8^3 = exp(-3i pi/4) (fwd) or conjugate (inv)
template <bool INV> __device__ __forceinline__ float2 rotW83(float2 z) {
    const float s = 0.70710678118654752440f;
    return INV ? make_float2(-s * (z.x + z.y), s * (z.x - z.y))
               : make_float2(s * (z.y - z.x), -s * (z.x + z.y));
}

// 8-point DFT (DIT), y_r = sum_j v_j W8^{jr} (conjugated for INV)
template <bool INV> __device__ __forceinline__ void fft8(float2 v[8]) {
    float2 a0 = cadd(v[0], v[4]), a1 = csub(v[0], v[4]);
    float2 a2 = cadd(v[2], v[6]), a3 = csub(v[2], v[6]);
    float2 b0 = cadd(v[1], v[5]), b1 = csub(v[1], v[5]);
    float2 b2 = cadd(v[3], v[7]), b3 = csub(v[3], v[7]);
    a3 = rot90<INV>(a3);
    b3 = rot90<INV>(b3);
    float2 E0 = cadd(a0, a2), E2 = csub(a0, a2);
    float2 E1 = cadd(a1, a3), E3 = csub(a1, a3);
    float2 O0 = cadd(b0, b2), O2 = csub(b0, b2);
    float2 O1 = cadd(b1, b3), O3 = csub(b1, b3);
    O1 = rotW81<INV>(O1);
    O2 = rot90<INV>(O2);
    O3 = rotW83<INV>(O3);
    v[0] = cadd(E0, O0); v[4] = csub(E0, O0);
    v[1] = cadd(E1, O1); v[5] = csub(E1, O1);
    v[2] = cadd(E2, O2); v[6] = csub(E2, O2);
    v[3] = cadd(E3, O3); v[7] = csub(E3, O3);
}

// ---------------------------------------------------------------------------
// Kernel A: build k[d, 0:4096] (concat of interpolated segments) + L2 norm.
// ---------------------------------------------------------------------------
__global__ __launch_bounds__(256) void build_k_kernel(
    const float* __restrict__ k0, const float* __restrict__ k1,
    const float* __restrict__ k2, const float* __restrict__ k3,
    const float* __restrict__ k4, const float* __restrict__ k5,
    const float* __restrict__ k6)
{
    int d = blockIdx.x;
    int tid = threadIdx.x;
    __shared__ float ssrc[7 * 64];
    __shared__ float sred[8];
    __shared__ float sinv;

    const float* ks[7] = {k0, k1, k2, k3, k4, k5, k6};
    for (int t = tid; t < 7 * 64; t += 256) {
        int i = t >> 6, j = t & 63;
        ssrc[t] = ks[i][d * 64 + j];
    }
    __syncthreads();

    float vals[16];
    float acc = 0.0f;
    #pragma unroll
    for (int r = 0; r < 16; r++) {
        int j = tid + r * 256;
        int i, off, lgs;
        if (j < 64)       { i = 0; off = 0;  lgs = 0; }
        else if (j < 128) { i = 1; off = 64; lgs = 0; }
        else {
            int t2 = 31 - __clz(j >> 6);
            i = t2 + 1; off = 64 << t2; lgs = t2;
        }
        int jj = j - off;
        float inv_s = 1.0f / (float)(1 << lgs);
        float c = (jj + 0.5f) * inv_s - 0.5f;
        c = fminf(fmaxf(c, 0.0f), 63.0f);
        float fl = floorf(c);
        int lo = (int)fl;
        int hi = min(lo + 1, 63);
        float w = c - fl;
        float v = ssrc[i * 64 + lo] * (1.0f - w) + ssrc[i * 64 + hi] * w;
        vals[r] = v;
        acc += v * v;
    }
    #pragma unroll
    for (int o = 16; o; o >>= 1) acc += __shfl_xor_sync(0xFFFFFFFFu, acc, o);
    if ((tid & 31) == 0) sred[tid >> 5] = acc;
    __syncthreads();
    if (tid == 0) {
        float s = 0.0f;
        #pragma unroll
        for (int i = 0; i < 8; i++) s += sred[i];
        sinv = 1.0f / sqrtf(s);
    }
    __syncthreads();
    float inv = sinv;
    #pragma unroll
    for (int r = 0; r < 16; r++)
        g_k[(size_t)d * LSEQ + tid + r * 256] = vals[r] * inv;
}

// ---------------------------------------------------------------------------
// Mixed-radix Stockham FFT, N=8192 = 8*8*8*8*2, out-of-place ping-pong.
// Stage order [8,8,8,8,2]: twiddle bases stay < N/8 -> 1024-entry table.
// Buffers are PAD()-indexed. Starts in bufA; result lands in bufB.
// ---------------------------------------------------------------------------
template <bool INV>
__device__ __forceinline__ void fft8192(float2* bufA, float2* bufB,
                                        const float2* __restrict__ tw, int tid)
{
    float2* s = bufA;
    float2* t = bufB;
    #pragma unroll
    for (int st = 0; st < 4; st++) {
        const int lgl = 3 * st;
        const int l = 1 << lgl;
        float2 v[8];
        #pragma unroll
        for (int j = 0; j < 8; j++) v[j] = s[PAD(tid + j * (NFFT / 8))];
        fft8<INV>(v);
        int q = tid & (l - 1);
        int p = tid >> lgl;
        int tb = p << lgl;               // twiddle base p*l, always < 1024
        if (tb) {
            float2 w1 = tw[tb];
            if (INV) w1.y = -w1.y;
            float2 w2 = cmul(w1, w1);
            float2 w3 = cmul(w2, w1);
            float2 w4 = cmul(w2, w2);
            v[1] = cmul(v[1], w1);
            v[2] = cmul(v[2], w2);
            v[3] = cmul(v[3], w3);
            v[4] = cmul(v[4], w4);
            v[5] = cmul(v[5], cmul(w4, w1));
            v[6] = cmul(v[6], cmul(w4, w2));
            v[7] = cmul(v[7], cmul(w4, w3));
        }
        int ob = q + (p << (lgl + 3));
        #pragma unroll
        for (int r = 0; r < 8; r++) t[PAD(ob + (r << lgl))] = v[r];
        __syncthreads();
        float2* tmp = s; s = t; t = tmp;
    }
    // final radix-2 stage, l = 4096: p == 0 -> no twiddle
    #pragma unroll
    for (int k = 0; k < 4; k++) {
        int i = tid + k * FFT_THREADS;       // 0..4095
        float2 a = s[PAD(i)];
        float2 b = s[PAD(i + 4096)];
        t[PAD(i)]        = cadd(a, b);
        t[PAD(i + 4096)] = csub(a, b);
    }
    __syncthreads();
}

// ---------------------------------------------------------------------------
// Kernel B: one CTA per d. Kernel FFT once (spectrum pre-scaled by 1/N in
// SMEM), then 8 batches as 4 complex-packed pairs: FFT, Hermitian split,
// spectral multiply, IFFT; epilogue fuses +D[d]*u and exact GELU.
// ---------------------------------------------------------------------------
__global__ __launch_bounds__(FFT_THREADS) void fft_conv_kernel(
    const float* __restrict__ u, const float* __restrict__ Dvec)
{
    extern __shared__ float2 smem[];
    float2* tw   = smem;                         // 1024 twiddles exp(-2pi i j/N)
    float2* Kf   = smem + 1024;                  // 8192 (unpadded)
    float2* bufA = smem + 1024 + 8192;           // 8704 (padded)
    float2* bufB = bufA + 8704;                  // 8704 (padded)

    int tid = threadIdx.x;
    int d = blockIdx.x;

    {
        float th = (-6.283185307179586f / (float)NFFT) * (float)tid;
        float sn, cs;
        sincosf(th, &sn, &cs);
        tw[tid] = make_float2(cs, sn);           // tid < 1024
    }
    #pragma unroll
    for (int k = 0; k < NFFT / FFT_THREADS; k++) {
        int j = tid + k * FFT_THREADS;
        bufA[PAD(j)] = make_float2(j < LSEQ ? g_k[(size_t)d * LSEQ + j] : 0.0f, 0.0f);
    }
    __syncthreads();

    fft8192<false>(bufA, bufB, tw, tid);
    const float scale = 1.0f / (float)NFFT;
    #pragma unroll
    for (int k = 0; k < NFFT / FFT_THREADS; k++) {
        int j = tid + k * FFT_THREADS;
        float2 kv = bufB[PAD(j)];
        Kf[j] = make_float2(kv.x * scale, kv.y * scale);
    }
    __syncthreads();

    float Dd = Dvec[d];
    for (int pr = 0; pr < BATCH / 2; pr++) {
        const float* u0 = u + ((size_t)(2 * pr)     * D_MODEL + d) * LSEQ;
        const float* u1 = u + ((size_t)(2 * pr + 1) * D_MODEL + d) * LSEQ;
        #pragma unroll
        for (int k = 0; k < NFFT / FFT_THREADS; k++) {
            int j = tid + k * FFT_THREADS;
            float a = (j < LSEQ) ? u0[j] : 0.0f;
            float b = (j < LSEQ) ? u1[j] : 0.0f;
            bufA[PAD(j)] = make_float2(a, b);
        }
        __syncthreads();
        fft8192<false>(bufA, bufB, tw, tid);     // Z in bufB

        #pragma unroll
        for (int k = 0; k < NFFT / FFT_THREADS; k++) {
            int j = tid + k * FFT_THREADS;
            int jn = (NFFT - j) & (NFFT - 1);
            float2 z  = bufB[PAD(j)];
            float2 zc = bufB[PAD(jn)];
            float2 U0 = make_float2(0.5f * (z.x + zc.x),  0.5f * (z.y - zc.y));
            float2 U1 = make_float2(0.5f * (z.y + zc.y), -0.5f * (z.x - zc.x));
            float2 kv = Kf[j];
            float2 y0 = cmul(U0, kv);
            float2 y1 = cmul(U1, kv);
            bufA[PAD(j)] = make_float2(y0.x - y1.y, y0.y + y1.x);   // Y0 + i*Y1
        }
        __syncthreads();
        fft8192<true>(bufA, bufB, tw, tid);      // w in bufB (1/N folded in Kf)

        float* g0 = g_gy + ((size_t)(2 * pr)     * D_MODEL + d) * LSEQ;
        float* g1 = g_gy + ((size_t)(2 * pr + 1) * D_MODEL + d) * LSEQ;
        #pragma unroll
        for (int k = 0; k < LSEQ / FFT_THREADS; k++) {
            int l = tid + k * FFT_THREADS;
            float2 wv = bufB[PAD(l)];
            float y0 = wv.x + Dd * u0[l];
            float y1 = wv.y + Dd * u1[l];
            g0[l] = 0.5f * y0 * (1.0f + erff(y0 * 0.7071067811865475f));
            g1[l] = 0.5f * y1 * (1.0f + erff(y1 * 0.7071067811865475f));
        }
        __syncthreads();
    }
}

// ---------------------------------------------------------------------------
// Kernel C: out[b,v,l] = sum_u W[v,u] * gy[b,u,l] + bias[v]
// tf32 mma m16n8k8, CTA 128x128x32, cp.async double-buffered, 8 warps.
// ---------------------------------------------------------------------------
__device__ __forceinline__ uint32_t f2tf(float f) {
    uint32_t r;
    asm("cvt.rna.tf32.f32 %0, %1;" : "=r"(r) : "f"(f));
    return r;
}
__device__ __forceinline__ void cp16(void* s, const void* g) {
    uint32_t sa = (uint32_t)__cvta_generic_to_shared(s);
    asm volatile("cp.async.cg.shared.global [%0], [%1], 16;" :: "r"(sa), "l"(g));
}
__device__ __forceinline__ void cp_commit() { asm volatile("cp.async.commit_group;"); }
template <int N> __device__ __forceinline__ void cp_wait() {
    asm volatile("cp.async.wait_group %0;" :: "n"(N));
}

#define GBM 128
#define GBN 128
#define GBK 32
#define SA_LD (GBK + 4)      // 36 floats/row = 144 B (16B multiple)
#define SB_LD (GBN + 8)      // 136 floats/row = 544 B (16B multiple)
#define SA_SZ (GBM * SA_LD)
#define SB_SZ (GBK * SB_LD)
#define GEMM_SMEM ((2 * SA_SZ + 2 * SB_SZ) * sizeof(float))

__global__ __launch_bounds__(256) void gemm_kernel(
    const float* __restrict__ Wm, const float* __restrict__ bias,
    float* __restrict__ out)
{
    extern __shared__ float gsm[];
    float* sA = gsm;                 // [2][128][36]
    float* sB = gsm + 2 * SA_SZ;     // [2][32][136]

    int tid = threadIdx.x;
    int warp = tid >> 5, lane = tid & 31;
    int gid = lane >> 2, q = lane & 3;
    int wm = (warp & 3) * 32;
    int wn = (warp >> 2) * 64;
    int bm = blockIdx.x, bn = blockIdx.y, bb = blockIdx.z;

    const float* Ag = Wm + (size_t)(bm * GBM) * D_MODEL;
    const float* Bg = g_gy + (size_t)bb * D_MODEL * LSEQ + (size_t)(bn * GBN);

    // per-thread load coordinates (fixed across tiles)
    int aIdxRow[4], aIdxCol[4], bIdxRow[4], bIdxCol[4];
    #pragma unroll
    for (int r = 0; r < 4; r++) {
        int ia = r * 256 + tid;
        aIdxRow[r] = ia >> 3;  aIdxCol[r] = (ia & 7) << 2;
        bIdxRow[r] = ia >> 5;  bIdxCol[r] = (ia & 31) << 2;
    }

    auto issue_tile = [&](int buf, int kt) {
        float* a = sA + buf * SA_SZ;
        float* b = sB + buf * SB_SZ;
        #pragma unroll
        for (int r = 0; r < 4; r++)
            cp16(a + aIdxRow[r] * SA_LD + aIdxCol[r],
                 Ag + (size_t)aIdxRow[r] * D_MODEL + kt + aIdxCol[r]);
        #pragma unroll
        for (int r = 0; r < 4; r++)
            cp16(b + bIdxRow[r] * SB_LD + bIdxCol[r],
                 Bg + (size_t)(kt + bIdxRow[r]) * LSEQ + bIdxCol[r]);
        cp_commit();
    };

    float acc[2][8][4];
    #pragma unroll
    for (int a = 0; a < 2; a++)
        #pragma unroll
        for (int b = 0; b < 8; b++)
            #pragma unroll
            for (int c = 0; c < 4; c++) acc[a][b][c] = 0.0f;

    const int T = D_MODEL / GBK;     // 32 k-tiles
    issue_tile(0, 0);

    for (int t = 0; t < T; t++) {
        if (t + 1 < T) {
            issue_tile((t + 1) & 1, (t + 1) * GBK);
            cp_wait<1>();
        } else {
            cp_wait<0>();
        }
        __syncthreads();

        const float* a = sA + (t & 1) * SA_SZ;
        const float* b = sB + (t & 1) * SB_SZ;

        #pragma unroll
        for (int kk = 0; kk < GBK; kk += 8) {
            uint32_t afr[2][4];
            #pragma unroll
            for (int mi = 0; mi < 2; mi++) {
                int r0 = wm + mi * 16 + gid;
                afr[mi][0] = f2tf(a[(r0    ) * SA_LD + kk + q    ]);
                afr[mi][1] = f2tf(a[(r0 + 8) * SA_LD + kk + q    ]);
                afr[mi][2] = f2tf(a[(r0    ) * SA_LD + kk + q + 4]);
                afr[mi][3] = f2tf(a[(r0 + 8) * SA_LD + kk + q + 4]);
            }
            uint32_t bfr[8][2];
            #pragma unroll
            for (int ni = 0; ni < 8; ni++) {
                int c0 = wn + ni * 8 + gid;
                bfr[ni][0] = f2tf(b[(kk + q    ) * SB_LD + c0]);
                bfr[ni][1] = f2tf(b[(kk + q + 4) * SB_LD + c0]);
            }
            #pragma unroll
            for (int mi = 0; mi < 2; mi++)
                #pragma unroll
                for (int ni = 0; ni < 8; ni++) {
                    asm volatile(
                        "mma.sync.aligned.m16n8k8.row.col.f32.tf32.tf32.f32 "
                        "{%0,%1,%2,%3}, {%4,%5,%6,%7}, {%8,%9}, {%0,%1,%2,%3};\n"
                        : "+f"(acc[mi][ni][0]), "+f"(acc[mi][ni][1]),
                          "+f"(acc[mi][ni][2]), "+f"(acc[mi][ni][3])
                        : "r"(afr[mi][0]), "r"(afr[mi][1]),
                          "r"(afr[mi][2]), "r"(afr[mi][3]),
                          "r"(bfr[ni][0]), "r"(bfr[ni][1]));
                }
        }
        __syncthreads();
    }

    #pragma unroll
    for (int mi = 0; mi < 2; mi++) {
        int v0 = bm * GBM + wm + mi * 16 + gid;
        int v1 = v0 + 8;
        float b0v = bias[v0], b1v = bias[v1];
        #pragma unroll
        for (int ni = 0; ni < 8; ni++) {
            int col = bn * GBN + wn + ni * 8 + q * 2;
            float2 s0 = make_float2(acc[mi][ni][0] + b0v, acc[mi][ni][1] + b0v);
            float2 s1 = make_float2(acc[mi][ni][2] + b1v, acc[mi][ni][3] + b1v);
            *reinterpret_cast<float2*>(out + ((size_t)bb * D_MODEL + v0) * LSEQ + col) = s0;
            *reinterpret_cast<float2*>(out + ((size_t)bb * D_MODEL + v1) * LSEQ + col) = s1;
        }
    }
}

// ---------------------------------------------------------------------------
extern "C" void kernel_launch(void* const* d_in, const int* in_sizes, int n_in,
                              void* d_out, int out_size)
{
    const float* u  = (const float*)d_in[0];
    const float* k0 = (const float*)d_in[1];
    const float* k1 = (const float*)d_in[2];
    const float* k2 = (const float*)d_in[3];
    const float* k3 = (const float*)d_in[4];
    const float* k4 = (const float*)d_in[5];
    const float* k5 = (const float*)d_in[6];
    const float* k6 = (const float*)d_in[7];
    const float* Dv = (const float*)d_in[8];
    const float* Wm = (const float*)d_in[9];
    const float* bv = (const float*)d_in[10];
    float* out = (float*)d_out;

    build_k_kernel<<<D_MODEL, 256>>>(k0, k1, k2, k3, k4, k5, k6);

    // SMEM: 1024 tw + 8192 Kf + 2 x 8704 padded buffers = 26624 float2 = 212992 B
    const size_t fft_smem = (size_t)(1024 + 8192 + 2 * 8704) * sizeof(float2);
    cudaFuncSetAttribute(fft_conv_kernel,
                         cudaFuncAttributeMaxDynamicSharedMemorySize,
                         (int)fft_smem);
    fft_conv_kernel<<<D_MODEL, FFT_THREADS, fft_smem>>>(u, Dv);

    cudaFuncSetAttribute(gemm_kernel,
                         cudaFuncAttributeMaxDynamicSharedMemorySize,
                         (int)GEMM_SMEM);
    dim3 grid(D_MODEL / GBM, LSEQ / GBN, BATCH);
    gemm_kernel<<<grid, 256, GEMM_SMEM>>>(Wm, bv, out);
}

// round 7
// speedup vs baseline: 1.3914x; 1.0232x over previous
#include <cuda_runtime.h>
#include <cstdint>

#define D_MODEL 1024
#define LSEQ    4096
#define BATCH   8
#define NFFT    8192
#define FFT_THREADS 1024

// padded SMEM index: +1 float2 every 16 float2 (breaks stride-8/64 store conflicts)
#define PAD(i) ((i) + ((i) >> 4))

// scratch (device globals; no allocation allowed)
__device__ __align__(16) float g_k [D_MODEL * LSEQ];                 // 16 MB normalized kernel
__device__ __align__(16) float g_gy[(size_t)BATCH * D_MODEL * LSEQ]; // 128 MB gelu(conv) output

__device__ __forceinline__ float2 cmul(float2 a, float2 b) {
    return make_float2(a.x * b.x - a.y * b.y, a.x * b.y + a.y * b.x);
}
__device__ __forceinline__ float2 cadd(float2 a, float2 b) { return make_float2(a.x + b.x, a.y + b.y); }
__device__ __forceinline__ float2 csub(float2 a, float2 b) { return make_float2(a.x - b.x, a.y - b.y); }

// rotation by -i (fwd) / +i (inv)
template <bool INV> __device__ __forceinline__ float2 rot90(float2 z) {
    return INV ? make_float2(-z.y, z.x) : make_float2(z.y, -z.x);
}
// rotation by W8^1 = exp(-i pi/4) (fwd) or its conjugate (inv)
template <bool INV> __device__ __forceinline__ float2 rotW81(float2 z) {
    const float s = 0.70710678118654752440f;
    return INV ? make_float2(s * (z.x - z.y), s * (z.y + z.x))
               : make_float2(s * (z.x + z.y), s * (z.y - z.x));
}
// rotation by W8^3 = exp(-3i pi/4) (fwd) or conjugate (inv)
template <bool INV> __device__ __forceinline__ float2 rotW83(float2 z) {
    const float s = 0.70710678118654752440f;
    return INV ? make_float2(-s * (z.x + z.y), s * (z.x - z.y))
               : make_float2(s * (z.y - z.x), -s * (z.x + z.y));
}

// 8-point DFT (DIT), y_r = sum_j v_j W8^{jr} (conjugated for INV)
template <bool INV> __device__ __forceinline__ void fft8(float2 v[8]) {
    float2 a0 = cadd(v[0], v[4]), a1 = csub(v[0], v[4]);
    float2 a2 = cadd(v[2], v[6]), a3 = csub(v[2], v[6]);
    float2 b0 = cadd(v[1], v[5]), b1 = csub(v[1], v[5]);
    float2 b2 = cadd(v[3], v[7]), b3 = csub(v[3], v[7]);
    a3 = rot90<INV>(a3);
    b3 = rot90<INV>(b3);
    float2 E0 = cadd(a0, a2), E2 = csub(a0, a2);
    float2 E1 = cadd(a1, a3), E3 = csub(a1, a3);
    float2 O0 = cadd(b0, b2), O2 = csub(b0, b2);
    float2 O1 = cadd(b1, b3), O3 = csub(b1, b3);
    O1 = rotW81<INV>(O1);
    O2 = rot90<INV>(O2);
    O3 = rotW83<INV>(O3);
    v[0] = cadd(E0, O0); v[4] = csub(E0, O0);
    v[1] = cadd(E1, O1); v[5] = csub(E1, O1);
    v[2] = cadd(E2, O2); v[6] = csub(E2, O2);
    v[3] = cadd(E3, O3); v[7] = csub(E3, O3);
}

// ---------------------------------------------------------------------------
// Kernel A: build k[d, 0:4096] (concat of interpolated segments) + L2 norm.
// ---------------------------------------------------------------------------
__global__ __launch_bounds__(256) void build_k_kernel(
    const float* __restrict__ k0, const float* __restrict__ k1,
    const float* __restrict__ k2, const float* __restrict__ k3,
    const float* __restrict__ k4, const float* __restrict__ k5,
    const float* __restrict__ k6)
{
    int d = blockIdx.x;
    int tid = threadIdx.x;
    __shared__ float ssrc[7 * 64];
    __shared__ float sred[8];
    __shared__ float sinv;

    const float* ks[7] = {k0, k1, k2, k3, k4, k5, k6};
    for (int t = tid; t < 7 * 64; t += 256) {
        int i = t >> 6, j = t & 63;
        ssrc[t] = ks[i][d * 64 + j];
    }
    __syncthreads();

    float vals[16];
    float acc = 0.0f;
    #pragma unroll
    for (int r = 0; r < 16; r++) {
        int j = tid + r * 256;
        int i, off, lgs;
        if (j < 64)       { i = 0; off = 0;  lgs = 0; }
        else if (j < 128) { i = 1; off = 64; lgs = 0; }
        else {
            int t2 = 31 - __clz(j >> 6);
            i = t2 + 1; off = 64 << t2; lgs = t2;
        }
        int jj = j - off;
        float inv_s = 1.0f / (float)(1 << lgs);
        float c = (jj + 0.5f) * inv_s - 0.5f;
        c = fminf(fmaxf(c, 0.0f), 63.0f);
        float fl = floorf(c);
        int lo = (int)fl;
        int hi = min(lo + 1, 63);
        float w = c - fl;
        float v = ssrc[i * 64 + lo] * (1.0f - w) + ssrc[i * 64 + hi] * w;
        vals[r] = v;
        acc += v * v;
    }
    #pragma unroll
    for (int o = 16; o; o >>= 1) acc += __shfl_xor_sync(0xFFFFFFFFu, acc, o);
    if ((tid & 31) == 0) sred[tid >> 5] = acc;
    __syncthreads();
    if (tid == 0) {
        float s = 0.0f;
        #pragma unroll
        for (int i = 0; i < 8; i++) s += sred[i];
        sinv = 1.0f / sqrtf(s);
    }
    __syncthreads();
    float inv = sinv;
    #pragma unroll
    for (int r = 0; r < 16; r++)
        g_k[(size_t)d * LSEQ + tid + r * 256] = vals[r] * inv;
}

// ---------------------------------------------------------------------------
// Mixed-radix Stockham FFT, N=8192 = 8*8*8*8*2, out-of-place ping-pong.
// Stage order [8,8,8,8,2]: twiddle bases stay < N/8 -> 1024-entry table.
// Buffers are PAD()-indexed. Starts in bufA; result lands in bufB.
// ---------------------------------------------------------------------------
template <bool INV>
__device__ __forceinline__ void fft8192(float2* bufA, float2* bufB,
                                        const float2* __restrict__ tw, int tid)
{
    float2* s = bufA;
    float2* t = bufB;
    #pragma unroll
    for (int st = 0; st < 4; st++) {
        const int lgl = 3 * st;
        const int l = 1 << lgl;
        float2 v[8];
        #pragma unroll
        for (int j = 0; j < 8; j++) v[j] = s[PAD(tid + j * (NFFT / 8))];
        fft8<INV>(v);
        int q = tid & (l - 1);
        int p = tid >> lgl;
        int tb = p << lgl;               // twiddle base p*l, always < 1024
        if (tb) {
            float2 w1 = tw[tb];
            if (INV) w1.y = -w1.y;
            float2 w2 = cmul(w1, w1);
            float2 w3 = cmul(w2, w1);
            float2 w4 = cmul(w2, w2);
            v[1] = cmul(v[1], w1);
            v[2] = cmul(v[2], w2);
            v[3] = cmul(v[3], w3);
            v[4] = cmul(v[4], w4);
            v[5] = cmul(v[5], cmul(w4, w1));
            v[6] = cmul(v[6], cmul(w4, w2));
            v[7] = cmul(v[7], cmul(w4, w3));
        }
        int ob = q + (p << (lgl + 3));
        #pragma unroll
        for (int r = 0; r < 8; r++) t[PAD(ob + (r << lgl))] = v[r];
        __syncthreads();
        float2* tmp = s; s = t; t = tmp;
    }
    // final radix-2 stage, l = 4096: p == 0 -> no twiddle
    #pragma unroll
    for (int k = 0; k < 4; k++) {
        int i = tid + k * FFT_THREADS;       // 0..4095
        float2 a = s[PAD(i)];
        float2 b = s[PAD(i + 4096)];
        t[PAD(i)]        = cadd(a, b);
        t[PAD(i + 4096)] = csub(a, b);
    }
    __syncthreads();
}

// ---------------------------------------------------------------------------
// Kernel B: one CTA per d. Kernel FFT once (spectrum pre-scaled by 1/N in
// SMEM), then 8 batches as 4 complex-packed pairs: FFT, Hermitian split,
// spectral multiply, IFFT; epilogue fuses +D[d]*u and exact GELU.
// ---------------------------------------------------------------------------
__global__ __launch_bounds__(FFT_THREADS) void fft_conv_kernel(
    const float* __restrict__ u, const float* __restrict__ Dvec)
{
    extern __shared__ float2 smem[];
    float2* tw   = smem;                         // 1024 twiddles exp(-2pi i j/N)
    float2* Kf   = smem + 1024;                  // 8192 (unpadded)
    float2* bufA = smem + 1024 + 8192;           // 8704 (padded)
    float2* bufB = bufA + 8704;                  // 8704 (padded)

    int tid = threadIdx.x;
    int d = blockIdx.x;

    {
        float th = (-6.283185307179586f / (float)NFFT) * (float)tid;
        float sn, cs;
        sincosf(th, &sn, &cs);
        tw[tid] = make_float2(cs, sn);           // tid < 1024
    }
    #pragma unroll
    for (int k = 0; k < NFFT / FFT_THREADS; k++) {
        int j = tid + k * FFT_THREADS;
        bufA[PAD(j)] = make_float2(j < LSEQ ? g_k[(size_t)d * LSEQ + j] : 0.0f, 0.0f);
    }
    __syncthreads();

    fft8192<false>(bufA, bufB, tw, tid);
    const float scale = 1.0f / (float)NFFT;
    #pragma unroll
    for (int k = 0; k < NFFT / FFT_THREADS; k++) {
        int j = tid + k * FFT_THREADS;
        float2 kv = bufB[PAD(j)];
        Kf[j] = make_float2(kv.x * scale, kv.y * scale);
    }
    __syncthreads();

    float Dd = Dvec[d];
    for (int pr = 0; pr < BATCH / 2; pr++) {
        const float* u0 = u + ((size_t)(2 * pr)     * D_MODEL + d) * LSEQ;
        const float* u1 = u + ((size_t)(2 * pr + 1) * D_MODEL + d) * LSEQ;
        #pragma unroll
        for (int k = 0; k < NFFT / FFT_THREADS; k++) {
            int j = tid + k * FFT_THREADS;
            float a = (j < LSEQ) ? u0[j] : 0.0f;
            float b = (j < LSEQ) ? u1[j] : 0.0f;
            bufA[PAD(j)] = make_float2(a, b);
        }
        __syncthreads();
        fft8192<false>(bufA, bufB, tw, tid);     // Z in bufB

        #pragma unroll
        for (int k = 0; k < NFFT / FFT_THREADS; k++) {
            int j = tid + k * FFT_THREADS;
            int jn = (NFFT - j) & (NFFT - 1);
            float2 z  = bufB[PAD(j)];
            float2 zc = bufB[PAD(jn)];
            float2 U0 = make_float2(0.5f * (z.x + zc.x),  0.5f * (z.y - zc.y));
            float2 U1 = make_float2(0.5f * (z.y + zc.y), -0.5f * (z.x - zc.x));
            float2 kv = Kf[j];
            float2 y0 = cmul(U0, kv);
            float2 y1 = cmul(U1, kv);
            bufA[PAD(j)] = make_float2(y0.x - y1.y, y0.y + y1.x);   // Y0 + i*Y1
        }
        __syncthreads();
        fft8192<true>(bufA, bufB, tw, tid);      // w in bufB (1/N folded in Kf)

        float* g0 = g_gy + ((size_t)(2 * pr)     * D_MODEL + d) * LSEQ;
        float* g1 = g_gy + ((size_t)(2 * pr + 1) * D_MODEL + d) * LSEQ;
        #pragma unroll
        for (int k = 0; k < LSEQ / FFT_THREADS; k++) {
            int l = tid + k * FFT_THREADS;
            float2 wv = bufB[PAD(l)];
            float y0 = wv.x + Dd * u0[l];
            float y1 = wv.y + Dd * u1[l];
            g0[l] = 0.5f * y0 * (1.0f + erff(y0 * 0.7071067811865475f));
            g1[l] = 0.5f * y1 * (1.0f + erff(y1 * 0.7071067811865475f));
        }
        __syncthreads();
    }
}

// ---------------------------------------------------------------------------
// Kernel C: out[b,v,l] = sum_u W[v,u] * gy[b,u,l] + bias[v]
// tf32 mma m16n8k8, CTA 128x128x32, cp.async double-buffered, 8 warps.
// ---------------------------------------------------------------------------
__device__ __forceinline__ uint32_t f2tf(float f) {
    uint32_t r;
    asm("cvt.rna.tf32.f32 %0, %1;" : "=r"(r) : "f"(f));
    return r;
}
__device__ __forceinline__ void cp16(void* s, const void* g) {
    uint32_t sa = (uint32_t)__cvta_generic_to_shared(s);
    asm volatile("cp.async.cg.shared.global [%0], [%1], 16;" :: "r"(sa), "l"(g));
}
__device__ __forceinline__ void cp_commit() { asm volatile("cp.async.commit_group;"); }
template <int N> __device__ __forceinline__ void cp_wait() {
    asm volatile("cp.async.wait_group %0;" :: "n"(N));
}

#define GBM 128
#define GBN 128
#define GBK 32
#define SA_LD (GBK + 4)      // 36 floats/row = 144 B (16B multiple)
#define SB_LD (GBN + 8)      // 136 floats/row = 544 B (16B multiple)
#define SA_SZ (GBM * SA_LD)
#define SB_SZ (GBK * SB_LD)
#define GEMM_SMEM ((2 * SA_SZ + 2 * SB_SZ) * sizeof(float))

__global__ __launch_bounds__(256) void gemm_kernel(
    const float* __restrict__ Wm, const float* __restrict__ bias,
    float* __restrict__ out)
{
    extern __shared__ float gsm[];
    float* sA = gsm;                 // [2][128][36]
    float* sB = gsm + 2 * SA_SZ;     // [2][32][136]

    int tid = threadIdx.x;
    int warp = tid >> 5, lane = tid & 31;
    int gid = lane >> 2, q = lane & 3;
    int wm = (warp & 3) * 32;
    int wn = (warp >> 2) * 64;
    int bm = blockIdx.x, bn = blockIdx.y, bb = blockIdx.z;

    const float* Ag = Wm + (size_t)(bm * GBM) * D_MODEL;
    const float* Bg = g_gy + (size_t)bb * D_MODEL * LSEQ + (size_t)(bn * GBN);

    // per-thread load coordinates (fixed across tiles)
    int aIdxRow[4], aIdxCol[4], bIdxRow[4], bIdxCol[4];
    #pragma unroll
    for (int r = 0; r < 4; r++) {
        int ia = r * 256 + tid;
        aIdxRow[r] = ia >> 3;  aIdxCol[r] = (ia & 7) << 2;
        bIdxRow[r] = ia >> 5;  bIdxCol[r] = (ia & 31) << 2;
    }

    auto issue_tile = [&](int buf, int kt) {
        float* a = sA + buf * SA_SZ;
        float* b = sB + buf * SB_SZ;
        #pragma unroll
        for (int r = 0; r < 4; r++)
            cp16(a + aIdxRow[r] * SA_LD + aIdxCol[r],
                 Ag + (size_t)aIdxRow[r] * D_MODEL + kt + aIdxCol[r]);
        #pragma unroll
        for (int r = 0; r < 4; r++)
            cp16(b + bIdxRow[r] * SB_LD + bIdxCol[r],
                 Bg + (size_t)(kt + bIdxRow[r]) * LSEQ + bIdxCol[r]);
        cp_commit();
    };

    float acc[2][8][4];
    #pragma unroll
    for (int a = 0; a < 2; a++)
        #pragma unroll
        for (int b = 0; b < 8; b++)
            #pragma unroll
            for (int c = 0; c < 4; c++) acc[a][b][c] = 0.0f;

    const int T = D_MODEL / GBK;     // 32 k-tiles
    issue_tile(0, 0);

    for (int t = 0; t < T; t++) {
        if (t + 1 < T) {
            issue_tile((t + 1) & 1, (t + 1) * GBK);
            cp_wait<1>();
        } else {
            cp_wait<0>();
        }
        __syncthreads();

        const float* a = sA + (t & 1) * SA_SZ;
        const float* b = sB + (t & 1) * SB_SZ;

        #pragma unroll
        for (int kk = 0; kk < GBK; kk += 8) {
            uint32_t afr[2][4];
            #pragma unroll
            for (int mi = 0; mi < 2; mi++) {
                int r0 = wm + mi * 16 + gid;
                afr[mi][0] = f2tf(a[(r0    ) * SA_LD + kk + q    ]);
                afr[mi][1] = f2tf(a[(r0 + 8) * SA_LD + kk + q    ]);
                afr[mi][2] = f2tf(a[(r0    ) * SA_LD + kk + q + 4]);
                afr[mi][3] = f2tf(a[(r0 + 8) * SA_LD + kk + q + 4]);
            }
            uint32_t bfr[8][2];
            #pragma unroll
            for (int ni = 0; ni < 8; ni++) {
                int c0 = wn + ni * 8 + gid;
                bfr[ni][0] = f2tf(b[(kk + q    ) * SB_LD + c0]);
                bfr[ni][1] = f2tf(b[(kk + q + 4) * SB_LD + c0]);
            }
            #pragma unroll
            for (int mi = 0; mi < 2; mi++)
                #pragma unroll
                for (int ni = 0; ni < 8; ni++) {
                    asm volatile(
                        "mma.sync.aligned.m16n8k8.row.col.f32.tf32.tf32.f32 "
                        "{%0,%1,%2,%3}, {%4,%5,%6,%7}, {%8,%9}, {%0,%1,%2,%3};\n"
                        : "+f"(acc[mi][ni][0]), "+f"(acc[mi][ni][1]),
                          "+f"(acc[mi][ni][2]), "+f"(acc[mi][ni][3])
                        : "r"(afr[mi][0]), "r"(afr[mi][1]),
                          "r"(afr[mi][2]), "r"(afr[mi][3]),
                          "r"(bfr[ni][0]), "r"(bfr[ni][1]));
                }
        }
        __syncthreads();
    }

    #pragma unroll
    for (int mi = 0; mi < 2; mi++) {
        int v0 = bm * GBM + wm + mi * 16 + gid;
        int v1 = v0 + 8;
        float b0v = bias[v0], b1v = bias[v1];
        #pragma unroll
        for (int ni = 0; ni < 8; ni++) {
            int col = bn * GBN + wn + ni * 8 + q * 2;
            float2 s0 = make_float2(acc[mi][ni][0] + b0v, acc[mi][ni][1] + b0v);
            float2 s1 = make_float2(acc[mi][ni][2] + b1v, acc[mi][ni][3] + b1v);
            *reinterpret_cast<float2*>(out + ((size_t)bb * D_MODEL + v0) * LSEQ + col) = s0;
            *reinterpret_cast<float2*>(out + ((size_t)bb * D_MODEL + v1) * LSEQ + col) = s1;
        }
    }
}

// ---------------------------------------------------------------------------
extern "C" void kernel_launch(void* const* d_in, const int* in_sizes, int n_in,
                              void* d_out, int out_size)
{
    const float* u  = (const float*)d_in[0];
    const float* k0 = (const float*)d_in[1];
    const float* k1 = (const float*)d_in[2];
    const float* k2 = (const float*)d_in[3];
    const float* k3 = (const float*)d_in[4];
    const float* k4 = (const float*)d_in[5];
    const float* k5 = (const float*)d_in[6];
    const float* k6 = (const float*)d_in[7];
    const float* Dv = (const float*)d_in[8];
    const float* Wm = (const float*)d_in[9];
    const float* bv = (const float*)d_in[10];
    float* out = (float*)d_out;

    build_k_kernel<<<D_MODEL, 256>>>(k0, k1, k2, k3, k4, k5, k6);

    // SMEM: 1024 tw + 8192 Kf + 2 x 8704 padded buffers = 26624 float2 = 212992 B
    const size_t fft_smem = (size_t)(1024 + 8192 + 2 * 8704) * sizeof(float2);
    cudaFuncSetAttribute(fft_conv_kernel,
                         cudaFuncAttributeMaxDynamicSharedMemorySize,
                         (int)fft_smem);
    fft_conv_kernel<<<D_MODEL, FFT_THREADS, fft_smem>>>(u, Dv);

    cudaFuncSetAttribute(gemm_kernel,
                         cudaFuncAttributeMaxDynamicSharedMemorySize,
                         (int)GEMM_SMEM);
    dim3 grid(D_MODEL / GBM, LSEQ / GBN, BATCH);
    gemm_kernel<<<grid, 256, GEMM_SMEM>>>(Wm, bv, out);
}